// round 9
// baseline (speedup 1.0000x reference)
#include <cuda_runtime.h>

#define NN   100000
#define EE   1600000
#define FIN  128
#define FOUT 32
#define CAP  128          // bucket capacity per node (Poisson(16) tail << 1e-60)

// ---------------- scratch (device globals; no allocation) ----------------
__device__ float g_inv_sigma;
__device__ float g_xw[NN * FOUT];        // 12.8 MB
__device__ int   g_cnt[NN];
__device__ int   g_src[NN * CAP];        // 51.2 MB bucket storage
__device__ int   g_idx64;                // 1 if edge_index is int64, 0 if int32

// ---------------- packed f32x2 helpers ----------------
__device__ __forceinline__ unsigned long long f2_fma(unsigned long long a,
                                                     unsigned long long b,
                                                     unsigned long long c) {
    unsigned long long d;
    asm("fma.rn.f32x2 %0, %1, %2, %3;" : "=l"(d) : "l"(a), "l"(b), "l"(c));
    return d;
}
__device__ __forceinline__ unsigned long long f2_dup(float v) {
    unsigned long long d;
    asm("mov.b64 %0, {%1, %1};" : "=l"(d) : "f"(v));
    return d;
}
__device__ __forceinline__ float2 f2_unpack(unsigned long long v) {
    float2 r;
    asm("mov.b64 {%0, %1}, %2;" : "=f"(r.x), "=f"(r.y) : "l"(v));
    return r;
}

// ---------------- 1. init: zero counters; block 0 = idx detect + sigma -----
__global__ void init_kernel(const void* __restrict__ ei,
                            const float* __restrict__ W,
                            const float* __restrict__ u) {
    int i = blockIdx.x * 256 + threadIdx.x;
    if (i < NN) g_cnt[i] = 0;

    if (blockIdx.x == 0) {
        int t = threadIdx.x;
        // warp 7: index dtype detection (independent of sigma)
        if ((t >> 5) == 7) {
            const long long* p = (const long long*)ei;
            int lt = t & 31;
            int bad = 0;
            for (int k = lt; k < 128; k += 32) {
                long long v = p[k];
                if (v < 0 || v >= NN) bad = 1;
            }
            bad = __any_sync(0xFFFFFFFF, bad);
            if (lt == 0) g_idx64 = bad ? 0 : 1;
        }
        // sigma = || W @ normalize(W^T u) ||  (threads 0..127)
        __shared__ float v[FIN];
        __shared__ float red[FIN];
        if (t < 128) {
            float s = 0.f;
#pragma unroll
            for (int j = 0; j < FOUT; j++) s += W[j * FIN + t] * u[j];
            v[t] = s;
            red[t] = s * s;
        }
        __syncthreads();
        for (int off = 64; off > 0; off >>= 1) {
            if (t < off) red[t] += red[t + off];
            __syncthreads();
        }
        float inv_nv = rsqrtf(fmaxf(red[0], 1e-24f));
        __syncthreads();
        if (t < 128) {
            float wv = 0.f;
            if (t < FOUT) {
#pragma unroll
                for (int k = 0; k < FIN; k++) wv += W[t * FIN + k] * v[k];
                wv *= inv_nv;
            }
            red[t] = (t < FOUT) ? wv * wv : 0.f;
        }
        __syncthreads();
        for (int off = 64; off > 0; off >>= 1) {
            if (t < off) red[t] += red[t + off];
            __syncthreads();
        }
        if (t == 0) {
            float sigma = sqrtf(red[0]);
            g_inv_sigma = 1.0f / fmaxf(sigma, 1e-12f);
        }
    }
}

// ---------------- 2. bucket fill (degree + CSR in ONE pass) ----------------
// 1 edge per thread: latency-bound kernel, maximize warps in flight
__global__ void bucket_kernel(const void* __restrict__ ei) {
    int e = blockIdx.x * 256 + threadIdx.x;
    if (e >= EE) return;
    int r, c;
    if (g_idx64) {
        const long long* p = (const long long*)ei;
        r = (int)p[e];
        c = (int)p[EE + e];
    } else {
        const int* p = (const int*)ei;
        r = p[e];
        c = p[EE + e];
    }
    int s = atomicAdd(&g_cnt[c], 1);
    if (s < CAP) g_src[c * CAP + s] = r;
}

// ---------------- 3. GEMM  xw = x @ W^T  (packed f32x2) --------------------
// 256 threads, 64 nodes/block; thread -> 2 nodes x 4 outputs
__global__ void gemm_kernel(const float* __restrict__ x, const float* __restrict__ W) {
    __shared__ float xs[64][132];
    __shared__ float wt[FIN][FOUT];     // wt[k][j]
    int tid = threadIdx.x;
    int n0 = blockIdx.x * 64;

    for (int i = tid; i < FIN * FOUT; i += 256) {
        int j = i >> 7, k = i & 127;
        wt[k][j] = W[i];
    }
    const float4* x4 = (const float4*)x;
    for (int i = tid; i < 64 * 32; i += 256) {
        int n = i >> 5, kc = i & 31;
        int gn = n0 + n;
        float4 vv = make_float4(0.f, 0.f, 0.f, 0.f);
        if (gn < NN) vv = x4[(long long)gn * 32 + kc];
        *(float4*)&xs[n][kc * 4] = vv;
    }
    __syncthreads();

    int np = tid >> 3;                 // node pair 0..31
    int na = np * 2, nb = np * 2 + 1;
    int j0 = (tid & 7) << 2;
    unsigned long long aA01 = 0ull, aA23 = 0ull, aB01 = 0ull, aB23 = 0ull;

#pragma unroll
    for (int kc = 0; kc < 32; kc++) {
        float4 xa = *(const float4*)&xs[na][kc << 2];
        float4 xb = *(const float4*)&xs[nb][kc << 2];
#pragma unroll
        for (int kk = 0; kk < 4; kk++) {
            ulonglong2 w = *(const ulonglong2*)&wt[(kc << 2) + kk][j0];
            float xav = (kk == 0) ? xa.x : (kk == 1) ? xa.y : (kk == 2) ? xa.z : xa.w;
            float xbv = (kk == 0) ? xb.x : (kk == 1) ? xb.y : (kk == 2) ? xb.z : xb.w;
            unsigned long long xad = f2_dup(xav);
            unsigned long long xbd = f2_dup(xbv);
            aA01 = f2_fma(w.x, xad, aA01);
            aA23 = f2_fma(w.y, xad, aA23);
            aB01 = f2_fma(w.x, xbd, aB01);
            aB23 = f2_fma(w.y, xbd, aB23);
        }
    }

    int ga = n0 + na, gb = n0 + nb;
    if (ga < NN) {
        float2 p0 = f2_unpack(aA01), p1 = f2_unpack(aA23);
        float4 r; r.x = p0.x; r.y = p0.y; r.z = p1.x; r.w = p1.y;
        *(float4*)&g_xw[ga * FOUT + j0] = r;
    }
    if (gb < NN) {
        float2 p0 = f2_unpack(aB01), p1 = f2_unpack(aB23);
        float4 r; r.x = p0.x; r.y = p0.y; r.z = p1.x; r.w = p1.y;
        *(float4*)&g_xw[gb * FOUT + j0] = r;
    }
}

// ---------------- 4. gather + self-loop + sigma + bias + PReLU ------------
// one warp per node, lane = feature; dis computed inline from cnt
__global__ void gather_kernel(float* __restrict__ out,
                              const float* __restrict__ bias,
                              const float* __restrict__ pa) {
    int warp = (blockIdx.x * 256 + threadIdx.x) >> 5;
    int lane = threadIdx.x & 31;
    if (warp >= NN) return;
    int node = warp;

    int deg = g_cnt[node];
    float dc = rsqrtf((float)(deg + 1));
    float acc = g_xw[node * 32 + lane] * dc * dc;   // self loop

    const int* bucket = &g_src[node * CAP];
    if (deg > CAP) deg = CAP;
    int j = 0;
#pragma unroll 1
    for (; j + 4 <= deg; j += 4) {
        int r0 = __ldg(&bucket[j + 0]);
        int r1 = __ldg(&bucket[j + 1]);
        int r2 = __ldg(&bucket[j + 2]);
        int r3 = __ldg(&bucket[j + 3]);
        int d0 = __ldg(&g_cnt[r0]);
        int d1 = __ldg(&g_cnt[r1]);
        int d2 = __ldg(&g_cnt[r2]);
        int d3 = __ldg(&g_cnt[r3]);
        float v0 = __ldg(&g_xw[r0 * 32 + lane]);
        float v1 = __ldg(&g_xw[r1 * 32 + lane]);
        float v2 = __ldg(&g_xw[r2 * 32 + lane]);
        float v3 = __ldg(&g_xw[r3 * 32 + lane]);
        float n0 = rsqrtf((float)(d0 + 1));
        float n1 = rsqrtf((float)(d1 + 1));
        float n2 = rsqrtf((float)(d2 + 1));
        float n3 = rsqrtf((float)(d3 + 1));
        acc = fmaf(v0, n0 * dc, acc);
        acc = fmaf(v1, n1 * dc, acc);
        acc = fmaf(v2, n2 * dc, acc);
        acc = fmaf(v3, n3 * dc, acc);
    }
    for (; j < deg; j++) {
        int r = __ldg(&bucket[j]);
        float dn = rsqrtf((float)(__ldg(&g_cnt[r]) + 1));
        acc = fmaf(__ldg(&g_xw[r * 32 + lane]), dn * dc, acc);
    }

    float v = acc * g_inv_sigma + bias[lane];
    float a = pa[0];
    out[node * 32 + lane] = (v >= 0.f) ? v : a * v;
}

// ---------------- launch (single stream, 4 kernels) ----------------
extern "C" void kernel_launch(void* const* d_in, const int* in_sizes, int n_in,
                              void* d_out, int out_size) {
    const float* x    = (const float*)d_in[0];
    const void*  ei   = d_in[1];
    const float* W    = (const float*)d_in[2];
    const float* bias = (const float*)d_in[3];
    const float* pa   = (const float*)d_in[4];
    const float* u    = (const float*)d_in[5];
    float*       out  = (float*)d_out;

    init_kernel<<<(NN + 255) / 256, 256>>>(ei, W, u);
    bucket_kernel<<<(EE + 255) / 256, 256>>>(ei);
    gemm_kernel<<<(NN + 63) / 64, 256>>>(x, W);
    gather_kernel<<<(NN * 32 + 255) / 256, 256>>>(out, bias, pa);
}

// round 10
// speedup vs baseline: 1.0879x; 1.0879x over previous
#include <cuda_runtime.h>

#define NN   100000
#define EE   1600000
#define FIN  128
#define FOUT 32
#define CAP  128          // bucket capacity per node (Poisson(16) tail << 1e-60)

// ---------------- scratch (device globals; no allocation) ----------------
__device__ float g_inv_sigma;
__device__ float g_xw[NN * FOUT];        // 12.8 MB
__device__ int   g_cnt[NN];
__device__ int   g_src[NN * CAP];        // 51.2 MB bucket storage
__device__ int   g_idx64;                // 1 if edge_index is int64, 0 if int32

// ---------------- packed f32x2 helpers ----------------
__device__ __forceinline__ unsigned long long f2_fma(unsigned long long a,
                                                     unsigned long long b,
                                                     unsigned long long c) {
    unsigned long long d;
    asm("fma.rn.f32x2 %0, %1, %2, %3;" : "=l"(d) : "l"(a), "l"(b), "l"(c));
    return d;
}
__device__ __forceinline__ unsigned long long f2_dup(float v) {
    unsigned long long d;
    asm("mov.b64 %0, {%1, %1};" : "=l"(d) : "f"(v));
    return d;
}
__device__ __forceinline__ float2 f2_unpack(unsigned long long v) {
    float2 r;
    asm("mov.b64 {%0, %1}, %2;" : "=f"(r.x), "=f"(r.y) : "l"(v));
    return r;
}

// ---------------- 1. init: zero counters; block 0 = idx detect + sigma -----
__global__ void init_kernel(const void* __restrict__ ei,
                            const float* __restrict__ W,
                            const float* __restrict__ u) {
    int i = blockIdx.x * 256 + threadIdx.x;
    if (i < NN) g_cnt[i] = 0;

    if (blockIdx.x == 0) {
        int t = threadIdx.x;
        // warp 7: index dtype detection (independent of sigma)
        if ((t >> 5) == 7) {
            const long long* p = (const long long*)ei;
            int lt = t & 31;
            int bad = 0;
            for (int k = lt; k < 128; k += 32) {
                long long v = p[k];
                if (v < 0 || v >= NN) bad = 1;
            }
            bad = __any_sync(0xFFFFFFFF, bad);
            if (lt == 0) g_idx64 = bad ? 0 : 1;
        }
        // sigma = || W @ normalize(W^T u) ||  (threads 0..127)
        __shared__ float v[FIN];
        __shared__ float red[FIN];
        if (t < 128) {
            float s = 0.f;
#pragma unroll
            for (int j = 0; j < FOUT; j++) s += W[j * FIN + t] * u[j];
            v[t] = s;
            red[t] = s * s;
        }
        __syncthreads();
        for (int off = 64; off > 0; off >>= 1) {
            if (t < off) red[t] += red[t + off];
            __syncthreads();
        }
        float inv_nv = rsqrtf(fmaxf(red[0], 1e-24f));
        __syncthreads();
        if (t < 128) {
            float wv = 0.f;
            if (t < FOUT) {
#pragma unroll
                for (int k = 0; k < FIN; k++) wv += W[t * FIN + k] * v[k];
                wv *= inv_nv;
            }
            red[t] = (t < FOUT) ? wv * wv : 0.f;
        }
        __syncthreads();
        for (int off = 64; off > 0; off >>= 1) {
            if (t < off) red[t] += red[t + off];
            __syncthreads();
        }
        if (t == 0) {
            float sigma = sqrtf(red[0]);
            g_inv_sigma = 1.0f / fmaxf(sigma, 1e-12f);
        }
    }
}

// ---------------- 2. bucket fill (degree + CSR in ONE pass) ----------------
// 1 edge per thread: latency-bound kernel, maximize warps in flight
__global__ void bucket_kernel(const void* __restrict__ ei) {
    int e = blockIdx.x * 256 + threadIdx.x;
    if (e >= EE) return;
    int r, c;
    if (g_idx64) {
        const long long* p = (const long long*)ei;
        r = (int)p[e];
        c = (int)p[EE + e];
    } else {
        const int* p = (const int*)ei;
        r = p[e];
        c = p[EE + e];
    }
    int s = atomicAdd(&g_cnt[c], 1);
    if (s < CAP) g_src[c * CAP + s] = r;
}

// ---------------- 3. GEMM  xw = x @ W^T  (packed f32x2) --------------------
// 256 threads, 64 nodes/block; thread -> 2 nodes x 4 outputs
__global__ void gemm_kernel(const float* __restrict__ x, const float* __restrict__ W) {
    __shared__ float xs[64][132];
    __shared__ float wt[FIN][FOUT];     // wt[k][j]
    int tid = threadIdx.x;
    int n0 = blockIdx.x * 64;

    for (int i = tid; i < FIN * FOUT; i += 256) {
        int j = i >> 7, k = i & 127;
        wt[k][j] = W[i];
    }
    const float4* x4 = (const float4*)x;
    for (int i = tid; i < 64 * 32; i += 256) {
        int n = i >> 5, kc = i & 31;
        int gn = n0 + n;
        float4 vv = make_float4(0.f, 0.f, 0.f, 0.f);
        if (gn < NN) vv = x4[(long long)gn * 32 + kc];
        *(float4*)&xs[n][kc * 4] = vv;
    }
    __syncthreads();

    int np = tid >> 3;                 // node pair 0..31
    int na = np * 2, nb = np * 2 + 1;
    int j0 = (tid & 7) << 2;
    unsigned long long aA01 = 0ull, aA23 = 0ull, aB01 = 0ull, aB23 = 0ull;

#pragma unroll
    for (int kc = 0; kc < 32; kc++) {
        float4 xa = *(const float4*)&xs[na][kc << 2];
        float4 xb = *(const float4*)&xs[nb][kc << 2];
#pragma unroll
        for (int kk = 0; kk < 4; kk++) {
            ulonglong2 w = *(const ulonglong2*)&wt[(kc << 2) + kk][j0];
            float xav = (kk == 0) ? xa.x : (kk == 1) ? xa.y : (kk == 2) ? xa.z : xa.w;
            float xbv = (kk == 0) ? xb.x : (kk == 1) ? xb.y : (kk == 2) ? xb.z : xb.w;
            unsigned long long xad = f2_dup(xav);
            unsigned long long xbd = f2_dup(xbv);
            aA01 = f2_fma(w.x, xad, aA01);
            aA23 = f2_fma(w.y, xad, aA23);
            aB01 = f2_fma(w.x, xbd, aB01);
            aB23 = f2_fma(w.y, xbd, aB23);
        }
    }

    int ga = n0 + na, gb = n0 + nb;
    if (ga < NN) {
        float2 p0 = f2_unpack(aA01), p1 = f2_unpack(aA23);
        float4 r; r.x = p0.x; r.y = p0.y; r.z = p1.x; r.w = p1.y;
        *(float4*)&g_xw[ga * FOUT + j0] = r;
    }
    if (gb < NN) {
        float2 p0 = f2_unpack(aB01), p1 = f2_unpack(aB23);
        float4 r; r.x = p0.x; r.y = p0.y; r.z = p1.x; r.w = p1.y;
        *(float4*)&g_xw[gb * FOUT + j0] = r;
    }
}

// ---------------- 4. gather: 4 edges x float4 per warp iteration -----------
// lane -> (q = edge slot 0..3, f = feature quarter 0..7)
// per iter: 1 bucket LDG + 1 cnt LDG + 1 LDG.128 + 1 rsqrt + 4 FMA per lane
__global__ void gather_kernel(float* __restrict__ out,
                              const float* __restrict__ bias,
                              const float* __restrict__ pa) {
    int warp = (blockIdx.x * 256 + threadIdx.x) >> 5;
    int lane = threadIdx.x & 31;
    if (warp >= NN) return;
    int node = warp;
    int q = lane >> 3;        // edge slot within group of 4
    int f = lane & 7;         // float4 quarter of the 32-feature row

    int deg = g_cnt[node];
    float dc = rsqrtf((float)(deg + 1));
    int degc = deg > CAP ? CAP : deg;

    const int*    bucket = &g_src[node * CAP];
    const float4* xw4    = (const float4*)g_xw;

    float4 acc = make_float4(0.f, 0.f, 0.f, 0.f);

#pragma unroll 2
    for (int j = 0; j < degc; j += 4) {
        int e  = j + q;
        int ec = e < degc - 1 ? e : degc - 1;        // clamped (degc>0 inside loop)
        int r  = __ldg(&bucket[ec]);
        float w = (e < degc) ? rsqrtf((float)(__ldg(&g_cnt[r]) + 1)) * dc : 0.f;
        float4 v = __ldg(&xw4[r * 8 + f]);
        acc.x = fmaf(v.x, w, acc.x);
        acc.y = fmaf(v.y, w, acc.y);
        acc.z = fmaf(v.z, w, acc.z);
        acc.w = fmaf(v.w, w, acc.w);
    }

    // reduce across the 4 edge slots (lanes differing in bits 3..4)
#pragma unroll
    for (int m = 8; m <= 16; m <<= 1) {
        acc.x += __shfl_xor_sync(0xFFFFFFFF, acc.x, m);
        acc.y += __shfl_xor_sync(0xFFFFFFFF, acc.y, m);
        acc.z += __shfl_xor_sync(0xFFFFFFFF, acc.z, m);
        acc.w += __shfl_xor_sync(0xFFFFFFFF, acc.w, m);
    }

    if (q == 0) {
        float4 self = __ldg(&xw4[node * 8 + f]);
        float s    = dc * dc;
        float isig = g_inv_sigma;
        float4 b   = ((const float4*)bias)[f];
        float a    = pa[0];
        float4 o;
        o.x = (acc.x + self.x * s) * isig + b.x;
        o.y = (acc.y + self.y * s) * isig + b.y;
        o.z = (acc.z + self.z * s) * isig + b.z;
        o.w = (acc.w + self.w * s) * isig + b.w;
        o.x = (o.x >= 0.f) ? o.x : a * o.x;
        o.y = (o.y >= 0.f) ? o.y : a * o.y;
        o.z = (o.z >= 0.f) ? o.z : a * o.z;
        o.w = (o.w >= 0.f) ? o.w : a * o.w;
        ((float4*)out)[node * 8 + f] = o;
    }
}

// ---------------- launch (single stream, 4 kernels) ----------------
extern "C" void kernel_launch(void* const* d_in, const int* in_sizes, int n_in,
                              void* d_out, int out_size) {
    const float* x    = (const float*)d_in[0];
    const void*  ei   = d_in[1];
    const float* W    = (const float*)d_in[2];
    const float* bias = (const float*)d_in[3];
    const float* pa   = (const float*)d_in[4];
    const float* u    = (const float*)d_in[5];
    float*       out  = (float*)d_out;

    init_kernel<<<(NN + 255) / 256, 256>>>(ei, W, u);
    bucket_kernel<<<(EE + 255) / 256, 256>>>(ei);
    gemm_kernel<<<(NN + 63) / 64, 256>>>(x, W);
    gather_kernel<<<(NN * 32 + 255) / 256, 256>>>(out, bias, pa);
}

// round 11
// speedup vs baseline: 1.1066x; 1.0171x over previous
#include <cuda_runtime.h>

#define NN   100000
#define EE   1600000
#define FIN  128
#define FOUT 32
#define CAP  128          // bucket capacity per node (Poisson(16) tail << 1e-60)

// ---------------- scratch (device globals; no allocation) ----------------
__device__ float g_inv_sigma;
__device__ float g_xw[NN * FOUT];        // 12.8 MB
__device__ int   g_cnt[NN];
__device__ float g_dis[NN];
__device__ int   g_src[NN * CAP];        // 51.2 MB bucket storage
__device__ int   g_idx64;                // 1 if edge_index is int64, 0 if int32

// ---------------- packed f32x2 helpers ----------------
__device__ __forceinline__ unsigned long long f2_fma(unsigned long long a,
                                                     unsigned long long b,
                                                     unsigned long long c) {
    unsigned long long d;
    asm("fma.rn.f32x2 %0, %1, %2, %3;" : "=l"(d) : "l"(a), "l"(b), "l"(c));
    return d;
}
__device__ __forceinline__ unsigned long long f2_dup(float v) {
    unsigned long long d;
    asm("mov.b64 %0, {%1, %1};" : "=l"(d) : "f"(v));
    return d;
}
__device__ __forceinline__ float2 f2_unpack(unsigned long long v) {
    float2 r;
    asm("mov.b64 {%0, %1}, %2;" : "=f"(r.x), "=f"(r.y) : "l"(v));
    return r;
}

// ---------------- 1. init: zero counters; block 0 = idx detect + sigma -----
__global__ void init_kernel(const void* __restrict__ ei,
                            const float* __restrict__ W,
                            const float* __restrict__ u) {
    int i = blockIdx.x * 256 + threadIdx.x;
    if (i < NN) g_cnt[i] = 0;

    if (blockIdx.x == 0) {
        int t = threadIdx.x;
        // warp 7: index dtype detection (independent of sigma)
        if ((t >> 5) == 7) {
            const long long* p = (const long long*)ei;
            int lt = t & 31;
            int bad = 0;
            for (int k = lt; k < 128; k += 32) {
                long long v = p[k];
                if (v < 0 || v >= NN) bad = 1;
            }
            bad = __any_sync(0xFFFFFFFF, bad);
            if (lt == 0) g_idx64 = bad ? 0 : 1;
        }
        // sigma = || W @ normalize(W^T u) ||  (threads 0..127)
        __shared__ float v[FIN];
        __shared__ float red[FIN];
        if (t < 128) {
            float s = 0.f;
#pragma unroll
            for (int j = 0; j < FOUT; j++) s += W[j * FIN + t] * u[j];
            v[t] = s;
            red[t] = s * s;
        }
        __syncthreads();
        for (int off = 64; off > 0; off >>= 1) {
            if (t < off) red[t] += red[t + off];
            __syncthreads();
        }
        float inv_nv = rsqrtf(fmaxf(red[0], 1e-24f));
        __syncthreads();
        if (t < 128) {
            float wv = 0.f;
            if (t < FOUT) {
#pragma unroll
                for (int k = 0; k < FIN; k++) wv += W[t * FIN + k] * v[k];
                wv *= inv_nv;
            }
            red[t] = (t < FOUT) ? wv * wv : 0.f;
        }
        __syncthreads();
        for (int off = 64; off > 0; off >>= 1) {
            if (t < off) red[t] += red[t + off];
            __syncthreads();
        }
        if (t == 0) {
            float sigma = sqrtf(red[0]);
            g_inv_sigma = 1.0f / fmaxf(sigma, 1e-12f);
        }
    }
}

// ---------------- 2. bucket fill (degree + CSR in ONE pass) ----------------
// 1 edge per thread: latency-bound kernel, maximize warps in flight
__global__ void bucket_kernel(const void* __restrict__ ei) {
    int e = blockIdx.x * 256 + threadIdx.x;
    if (e >= EE) return;
    int r, c;
    if (g_idx64) {
        const long long* p = (const long long*)ei;
        r = (int)p[e];
        c = (int)p[EE + e];
    } else {
        const int* p = (const int*)ei;
        r = p[e];
        c = p[EE + e];
    }
    int s = atomicAdd(&g_cnt[c], 1);
    if (s < CAP) g_src[c * CAP + s] = r;
}

// ---------------- 3. GEMM  xw = x @ W^T  (packed f32x2) --------------------
// 256 threads, 64 nodes/block; thread -> 2 nodes x 4 outputs
// also: computes g_dis = rsqrt(cnt+1) (runs after bucket; cnt is final)
__global__ void gemm_kernel(const float* __restrict__ x, const float* __restrict__ W) {
    __shared__ float xs[64][132];
    __shared__ float wt[FIN][FOUT];     // wt[k][j]
    int tid = threadIdx.x;
    int n0 = blockIdx.x * 64;

    // piggyback: dis for one node per thread (grid covers NN with margin)
    int gi = blockIdx.x * 256 + tid;
    if (gi < NN) g_dis[gi] = rsqrtf((float)(g_cnt[gi] + 1));

    for (int i = tid; i < FIN * FOUT; i += 256) {
        int j = i >> 7, k = i & 127;
        wt[k][j] = W[i];
    }
    const float4* x4 = (const float4*)x;
    for (int i = tid; i < 64 * 32; i += 256) {
        int n = i >> 5, kc = i & 31;
        int gn = n0 + n;
        float4 vv = make_float4(0.f, 0.f, 0.f, 0.f);
        if (gn < NN) vv = x4[(long long)gn * 32 + kc];
        *(float4*)&xs[n][kc * 4] = vv;
    }
    __syncthreads();

    int np = tid >> 3;                 // node pair 0..31
    int na = np * 2, nb = np * 2 + 1;
    int j0 = (tid & 7) << 2;
    unsigned long long aA01 = 0ull, aA23 = 0ull, aB01 = 0ull, aB23 = 0ull;

#pragma unroll
    for (int kc = 0; kc < 32; kc++) {
        float4 xa = *(const float4*)&xs[na][kc << 2];
        float4 xb = *(const float4*)&xs[nb][kc << 2];
#pragma unroll
        for (int kk = 0; kk < 4; kk++) {
            ulonglong2 w = *(const ulonglong2*)&wt[(kc << 2) + kk][j0];
            float xav = (kk == 0) ? xa.x : (kk == 1) ? xa.y : (kk == 2) ? xa.z : xa.w;
            float xbv = (kk == 0) ? xb.x : (kk == 1) ? xb.y : (kk == 2) ? xb.z : xb.w;
            unsigned long long xad = f2_dup(xav);
            unsigned long long xbd = f2_dup(xbv);
            aA01 = f2_fma(w.x, xad, aA01);
            aA23 = f2_fma(w.y, xad, aA23);
            aB01 = f2_fma(w.x, xbd, aB01);
            aB23 = f2_fma(w.y, xbd, aB23);
        }
    }

    int ga = n0 + na, gb = n0 + nb;
    if (ga < NN) {
        float2 p0 = f2_unpack(aA01), p1 = f2_unpack(aA23);
        float4 r; r.x = p0.x; r.y = p0.y; r.z = p1.x; r.w = p1.y;
        *(float4*)&g_xw[ga * FOUT + j0] = r;
    }
    if (gb < NN) {
        float2 p0 = f2_unpack(aB01), p1 = f2_unpack(aB23);
        float4 r; r.x = p0.x; r.y = p0.y; r.z = p1.x; r.w = p1.y;
        *(float4*)&g_xw[gb * FOUT + j0] = r;
    }
}

// ---------------- 4. gather: 4 edges x float4 per warp iteration -----------
// lane -> (q = edge slot 0..3, f = feature quarter 0..7)
// inner iter: LDG bucket + LDG dis + LDG.128 xw + 4 FMA; dc folded into epilogue
__global__ void gather_kernel(float* __restrict__ out,
                              const float* __restrict__ bias,
                              const float* __restrict__ pa) {
    int warp = (blockIdx.x * 256 + threadIdx.x) >> 5;
    int lane = threadIdx.x & 31;
    if (warp >= NN) return;
    int node = warp;
    int q = lane >> 3;        // edge slot within group of 4
    int f = lane & 7;         // float4 quarter of the 32-feature row

    int deg = g_cnt[node];
    int degc = deg > CAP ? CAP : deg;

    const int*    bucket = &g_src[node * CAP];
    const float4* xw4    = (const float4*)g_xw;

    float4 acc = make_float4(0.f, 0.f, 0.f, 0.f);

#pragma unroll 4
    for (int j = 0; j < degc; j += 4) {
        int e  = j + q;
        int ec = e < degc - 1 ? e : degc - 1;        // clamped (degc>0 inside loop)
        int r  = __ldg(&bucket[ec]);
        float w = (e < degc) ? __ldg(&g_dis[r]) : 0.f;
        float4 v = __ldg(&xw4[r * 8 + f]);
        acc.x = fmaf(v.x, w, acc.x);
        acc.y = fmaf(v.y, w, acc.y);
        acc.z = fmaf(v.z, w, acc.z);
        acc.w = fmaf(v.w, w, acc.w);
    }

    // reduce across the 4 edge slots (lanes differing in bits 3..4)
#pragma unroll
    for (int m = 8; m <= 16; m <<= 1) {
        acc.x += __shfl_xor_sync(0xFFFFFFFF, acc.x, m);
        acc.y += __shfl_xor_sync(0xFFFFFFFF, acc.y, m);
        acc.z += __shfl_xor_sync(0xFFFFFFFF, acc.z, m);
        acc.w += __shfl_xor_sync(0xFFFFFFFF, acc.w, m);
    }

    if (q == 0) {
        float4 self = __ldg(&xw4[node * 8 + f]);
        float dc   = g_dis[node];
        float s    = dc * dc;
        float isig = g_inv_sigma;
        float4 b   = ((const float4*)bias)[f];
        float a    = pa[0];
        float4 o;
        o.x = (acc.x * dc + self.x * s) * isig + b.x;
        o.y = (acc.y * dc + self.y * s) * isig + b.y;
        o.z = (acc.z * dc + self.z * s) * isig + b.z;
        o.w = (acc.w * dc + self.w * s) * isig + b.w;
        o.x = (o.x >= 0.f) ? o.x : a * o.x;
        o.y = (o.y >= 0.f) ? o.y : a * o.y;
        o.z = (o.z >= 0.f) ? o.z : a * o.z;
        o.w = (o.w >= 0.f) ? o.w : a * o.w;
        ((float4*)out)[node * 8 + f] = o;
    }
}

// ---------------- launch (single stream, 4 kernels) ----------------
extern "C" void kernel_launch(void* const* d_in, const int* in_sizes, int n_in,
                              void* d_out, int out_size) {
    const float* x    = (const float*)d_in[0];
    const void*  ei   = d_in[1];
    const float* W    = (const float*)d_in[2];
    const float* bias = (const float*)d_in[3];
    const float* pa   = (const float*)d_in[4];
    const float* u    = (const float*)d_in[5];
    float*       out  = (float*)d_out;

    init_kernel<<<(NN + 255) / 256, 256>>>(ei, W, u);
    bucket_kernel<<<(EE + 255) / 256, 256>>>(ei);
    gemm_kernel<<<(NN + 63) / 64, 256>>>(x, W);
    gather_kernel<<<(NN * 32 + 255) / 256, 256>>>(out, bias, pa);
}